// round 15
// baseline (speedup 1.0000x reference)
#include <cuda_runtime.h>
#include <cuda_fp16.h>
#include <math.h>

#define MAXN 100000
#define MAXE 3200000
#define MAXG 1000
#define H  50
#define D3 15
#define D5 10
#define NC 6
#define EPS 1e-5f
#define TPB 128

// -------- scratch (device globals) --------
__device__ float g_x2sum[MAXN * 16];
__device__ float g_z[MAXG * D5];
__device__ float g_zstat[2 * D5];
__device__ float g_x4[MAXN * 4];
__device__ int   g_gstart[MAXG + 1];
__device__ int   g_cnt[MAXN];
__device__ int   g_off[MAXN];
__device__ uint4 g_esort[MAXE];   // row, col, h2(ea0,ea1), h2(ea2,0)

// -------- helpers --------
__device__ __forceinline__ unsigned packh2(float a, float b) {
    __half2 h = __floats2half2_rn(a, b);
    return *reinterpret_cast<unsigned*>(&h);
}
__device__ __forceinline__ unsigned packh2_relu(float a, float b) {
    return packh2(fmaxf(a, 0.f), fmaxf(b, 0.f));
}
__device__ __forceinline__ void mma16(float c[4], unsigned a0, unsigned a1, unsigned a2, unsigned a3,
                                      unsigned b0, unsigned b1) {
    asm volatile("mma.sync.aligned.m16n8k16.row.col.f32.f16.f16.f32 "
        "{%0,%1,%2,%3}, {%4,%5,%6,%7}, {%8,%9}, {%0,%1,%2,%3};"
        : "+f"(c[0]), "+f"(c[1]), "+f"(c[2]), "+f"(c[3])
        : "r"(a0), "r"(a1), "r"(a2), "r"(a3), "r"(b0), "r"(b1));
}
__device__ __forceinline__ void red_add_v4(float* dst, float a, float b, float c, float d) {
    asm volatile("red.global.add.v4.f32 [%0], {%1,%2,%3,%4};"
                 :: "l"(dst), "f"(a), "f"(b), "f"(c), "f"(d) : "memory");
}

// -------------------- zero scratch + pad x + graph boundaries ------------
__global__ void zero_kernel(const float* __restrict__ x, const int* __restrict__ batch,
                            int N, int G) {
    int i = blockIdx.x * blockDim.x + threadIdx.x;
    int stride = gridDim.x * blockDim.x;
    float4 z4 = make_float4(0.f, 0.f, 0.f, 0.f);
    float4* x2v = reinterpret_cast<float4*>(g_x2sum);
    int n16 = N * 4;
    for (int k = i; k < n16; k += stride) x2v[k] = z4;
    for (int k = i; k < N; k += stride) {
        float4 v;
        v.x = x[3 * k]; v.y = x[3 * k + 1]; v.z = x[3 * k + 2]; v.w = 0.f;
        *reinterpret_cast<float4*>(g_x4 + 4 * (size_t)k) = v;
        g_cnt[k] = 0;
    }
    for (int k = i; k < N; k += stride) {
        int b = batch[k];
        int bn = (k + 1 < N) ? batch[k + 1] : G;
        if (k == 0)
            for (int g = 0; g <= b; g++) g_gstart[g] = 0;
        for (int g = b + 1; g <= bn; g++) g_gstart[g] = k + 1;
    }
    if (i < 2 * D5) g_zstat[i] = 0.f;
}

// -------------------- histogram over destination (row) nodes -------------
__global__ void hist_kernel(const int* __restrict__ ei, int E) {
    int stride = gridDim.x * blockDim.x;
    for (int e = blockIdx.x * blockDim.x + threadIdx.x; e < E; e += stride)
        atomicAdd(&g_cnt[ei[e]], 1);
}

// -------------------- single-block exclusive scan over g_cnt -------------
__global__ __launch_bounds__(1024)
void scan_kernel(int N) {
    __shared__ int swarp[32];
    __shared__ int sbase[32];
    __shared__ int s_carry;
    int tid = threadIdx.x, lane = tid & 31, w = tid >> 5;
    if (tid == 0) s_carry = 0;
    __syncthreads();
    for (int base = 0; base < N; base += 1024) {
        int i = base + tid;
        int v = (i < N) ? g_cnt[i] : 0;
        int x = v;
        #pragma unroll
        for (int o = 1; o < 32; o <<= 1) {
            int y = __shfl_up_sync(0xffffffffu, x, o);
            if (lane >= o) x += y;
        }
        if (lane == 31) swarp[w] = x;
        __syncthreads();
        if (w == 0) {
            int s = swarp[lane];
            int xs = s;
            #pragma unroll
            for (int o = 1; o < 32; o <<= 1) {
                int y = __shfl_up_sync(0xffffffffu, xs, o);
                if (lane >= o) xs += y;
            }
            sbase[lane] = xs - s;
        }
        __syncthreads();
        int carry = s_carry;
        if (i < N) g_off[i] = carry + sbase[w] + x - v;
        __syncthreads();
        if (tid == 1023) s_carry = carry + sbase[31] + x;
        __syncthreads();
    }
}

// -------------------- scatter edges into sorted-by-row records -----------
__global__ void scatter_kernel(const int* __restrict__ ei, const float* __restrict__ ea, int E) {
    int stride = gridDim.x * blockDim.x;
    for (int e = blockIdx.x * blockDim.x + threadIdx.x; e < E; e += stride) {
        int row = ei[e];
        int col = ei[E + e];
        int pos = atomicAdd(&g_off[row], 1);
        uint4 rec;
        rec.x = (unsigned)row;
        rec.y = (unsigned)col;
        rec.z = packh2(ea[3 * e], ea[3 * e + 1]);
        rec.w = packh2(ea[3 * e + 2], 0.f);
        g_esort[pos] = rec;
    }
}

// -------------------- edge pipeline: fp16 MMA + segment-reduced scatter ---
__global__ __launch_bounds__(TPB, 3)
void edge_mma_kernel(const float* __restrict__ ew1, const float* __restrict__ eb1,
                     const float* __restrict__ ew2, const float* __restrict__ eb2,
                     const float* __restrict__ nw1, const float* __restrict__ nb1,
                     const float* __restrict__ nw2, const float* __restrict__ nb2,
                     int E, int ntiles)
{
    __shared__ unsigned uw1e[8 * 56];
    __shared__ unsigned uw2e[32 * 24];
    __shared__ unsigned uw1n[16 * 56];
    __shared__ unsigned uw2n[32 * 24];
    __shared__ float sb1e[56], sb2e[16], sb1n[56], sb2n[16];
    __shared__ unsigned ustg[4 * 32 * 12];
    __shared__ float smsg[4][32 * 20];   // per-warp message tile, stride 20

    int tid = threadIdx.x;

    for (int i = tid; i < 8 * 56; i += TPB) {
        int kp = i / 56, n = i % 56;
        int k0 = 2 * kp, k1 = 2 * kp + 1;
        float w0 = (k0 < 9 && n < 50) ? ew1[k0 * 50 + n] : 0.f;
        float w1 = (k1 < 9 && n < 50) ? ew1[k1 * 50 + n] : 0.f;
        uw1e[i] = packh2(w0, w1);
    }
    for (int i = tid; i < 32 * 24; i += TPB) {
        int kp = i / 24, n = i % 24;
        int k0 = 2 * kp, k1 = k0 + 1;
        float w0 = (k0 < 50 && n < 15) ? ew2[k0 * 15 + n] : 0.f;
        float w1 = (k1 < 50 && n < 15) ? ew2[k1 * 15 + n] : 0.f;
        uw2e[i] = packh2(w0, w1);
    }
    for (int i = tid; i < 16 * 56; i += TPB) {
        int kp = i / 56, n = i % 56;
        float w[2];
        #pragma unroll
        for (int h = 0; h < 2; h++) {
            int k = 2 * kp + h;
            int src = (k < 15) ? (3 + k) : ((k >= 16 && k < 19) ? (k - 16) : -1);
            w[h] = (src >= 0 && n < 50) ? nw1[src * 50 + n] : 0.f;
        }
        uw1n[i] = packh2(w[0], w[1]);
    }
    for (int i = tid; i < 32 * 24; i += TPB) {
        int kp = i / 24, n = i % 24;
        int k0 = 2 * kp, k1 = k0 + 1;
        float w0 = (k0 < 50 && n < 15) ? nw2[k0 * 15 + n] : 0.f;
        float w1 = (k1 < 50 && n < 15) ? nw2[k1 * 15 + n] : 0.f;
        uw2n[i] = packh2(w0, w1);
    }
    for (int i = tid; i < 56; i += TPB) sb1e[i] = (i < 50) ? eb1[i] : 0.f;
    for (int i = tid; i < 16; i += TPB) sb2e[i] = (i < 15) ? eb2[i] : 0.f;
    for (int i = tid; i < 56; i += TPB) sb1n[i] = (i < 50) ? nb1[i] : 0.f;
    for (int i = tid; i < 16; i += TPB) sb2n[i] = (i < 15) ? nb2[i] : 0.f;
    __syncthreads();

    int wid = tid >> 5, lane = tid & 31;
    int qid = lane >> 2, tq = lane & 3;
    unsigned* stg = ustg + wid * 384;
    float* msgw = smsg[wid];

    stg[lane * 12 + 5] = 0u; stg[lane * 12 + 6] = 0u; stg[lane * 12 + 7] = 0u;
    __syncwarp();

    for (int t = blockIdx.x; t < ntiles; t += gridDim.x) {
        int wbase = t * 128 + wid * 32;
        int e = wbase + lane;
        int el = (e < E) ? e : (E - 1);
        bool evalid = (e < E);
        uint4 rec = g_esort[el];
        int r = (int)rec.x;
        int c = (int)rec.y;
        float4 xr = *reinterpret_cast<const float4*>(g_x4 + 4 * (size_t)r);
        float4 xc4 = *reinterpret_cast<const float4*>(g_x4 + 4 * (size_t)c);
        float xc0 = xc4.x, xc1 = xc4.y, xc2 = xc4.z;

        {
            unsigned* sp = stg + lane * 12;
            sp[0] = packh2(xr.x, xr.y);
            sp[1] = packh2(xr.z, xc0);
            sp[2] = packh2(xc1, xc2);
            sp[3] = rec.z;
            sp[4] = rec.w;
        }
        __syncwarp();

        // ---- L1 ----
        unsigned a2f[2][4][4];
        #pragma unroll
        for (int mt = 0; mt < 2; mt++) {
            unsigned a0 = stg[(16 * mt + qid) * 12 + tq];
            unsigned a1 = stg[(16 * mt + 8 + qid) * 12 + tq];
            unsigned a2 = stg[(16 * mt + qid) * 12 + tq + 4];
            unsigned a3 = stg[(16 * mt + 8 + qid) * 12 + tq + 4];
            float C1[7][4];
            #pragma unroll
            for (int nt = 0; nt < 7; nt++) {
                float bx = sb1e[8 * nt + 2 * tq], by = sb1e[8 * nt + 2 * tq + 1];
                C1[nt][0] = bx; C1[nt][1] = by; C1[nt][2] = bx; C1[nt][3] = by;
                unsigned b0 = uw1e[tq * 56 + 8 * nt + qid];
                unsigned b1 = uw1e[(tq + 4) * 56 + 8 * nt + qid];
                mma16(C1[nt], a0, a1, a2, a3, b0, b1);
            }
            #pragma unroll
            for (int kt = 0; kt < 4; kt++) {
                a2f[mt][kt][0] = packh2_relu(C1[2 * kt][0], C1[2 * kt][1]);
                a2f[mt][kt][1] = packh2_relu(C1[2 * kt][2], C1[2 * kt][3]);
                if (kt < 3) {
                    a2f[mt][kt][2] = packh2_relu(C1[2 * kt + 1][0], C1[2 * kt + 1][1]);
                    a2f[mt][kt][3] = packh2_relu(C1[2 * kt + 1][2], C1[2 * kt + 1][3]);
                } else {
                    a2f[mt][kt][2] = 0u; a2f[mt][kt][3] = 0u;
                }
            }
        }
        __syncwarp();

        // ---- L2 ----
        float C2[2][2][4];
        #pragma unroll
        for (int mt = 0; mt < 2; mt++)
            #pragma unroll
            for (int nt = 0; nt < 2; nt++) {
                float bx = sb2e[8 * nt + 2 * tq], by = sb2e[8 * nt + 2 * tq + 1];
                float* cc = C2[mt][nt];
                cc[0] = bx; cc[1] = by; cc[2] = bx; cc[3] = by;
                #pragma unroll
                for (int kt = 0; kt < 4; kt++) {
                    unsigned b0 = uw2e[(kt * 8 + tq) * 24 + 8 * nt + qid];
                    unsigned b1 = uw2e[(kt * 8 + tq + 4) * 24 + 8 * nt + qid];
                    mma16(cc, a2f[mt][kt][0], a2f[mt][kt][1], a2f[mt][kt][2], a2f[mt][kt][3], b0, b1);
                }
            }

        // ---- L3 A frags ----
        unsigned a3f[2][2][4];
        #pragma unroll
        for (int mt = 0; mt < 2; mt++) {
            a3f[mt][0][0] = packh2(C2[mt][0][0], C2[mt][0][1]);
            a3f[mt][0][1] = packh2(C2[mt][0][2], C2[mt][0][3]);
            a3f[mt][0][2] = packh2(C2[mt][1][0], C2[mt][1][1]);
            a3f[mt][0][3] = packh2(C2[mt][1][2], C2[mt][1][3]);
            int row0 = 16 * mt + qid, row1 = row0 + 8;
            float p0 = __shfl_sync(0xffffffffu, xc0, row0);
            float p1 = __shfl_sync(0xffffffffu, xc1, row0);
            float p2 = __shfl_sync(0xffffffffu, xc2, row0);
            float q0 = __shfl_sync(0xffffffffu, xc0, row1);
            float q1 = __shfl_sync(0xffffffffu, xc1, row1);
            float q2 = __shfl_sync(0xffffffffu, xc2, row1);
            unsigned a0 = (tq == 0) ? packh2(p0, p1) : ((tq == 1) ? packh2(p2, 0.f) : 0u);
            unsigned a1 = (tq == 0) ? packh2(q0, q1) : ((tq == 1) ? packh2(q2, 0.f) : 0u);
            a3f[mt][1][0] = a0; a3f[mt][1][1] = a1;
            a3f[mt][1][2] = 0u; a3f[mt][1][3] = 0u;
        }

        // ---- L3 + L4 -> store messages to smem ----
        #pragma unroll
        for (int mt = 0; mt < 2; mt++) {
            float C3[7][4];
            #pragma unroll
            for (int nt = 0; nt < 7; nt++) {
                float bx = sb1n[8 * nt + 2 * tq], by = sb1n[8 * nt + 2 * tq + 1];
                C3[nt][0] = bx; C3[nt][1] = by; C3[nt][2] = bx; C3[nt][3] = by;
                #pragma unroll
                for (int kt = 0; kt < 2; kt++) {
                    unsigned b0 = uw1n[(kt * 8 + tq) * 56 + 8 * nt + qid];
                    unsigned b1 = uw1n[(kt * 8 + tq + 4) * 56 + 8 * nt + qid];
                    mma16(C3[nt], a3f[mt][kt][0], a3f[mt][kt][1], a3f[mt][kt][2], a3f[mt][kt][3], b0, b1);
                }
            }
            unsigned a4f[4][4];
            #pragma unroll
            for (int kt = 0; kt < 4; kt++) {
                a4f[kt][0] = packh2_relu(C3[2 * kt][0], C3[2 * kt][1]);
                a4f[kt][1] = packh2_relu(C3[2 * kt][2], C3[2 * kt][3]);
                if (kt < 3) {
                    a4f[kt][2] = packh2_relu(C3[2 * kt + 1][0], C3[2 * kt + 1][1]);
                    a4f[kt][3] = packh2_relu(C3[2 * kt + 1][2], C3[2 * kt + 1][3]);
                } else {
                    a4f[kt][2] = 0u; a4f[kt][3] = 0u;
                }
            }
            float C4[2][4];
            #pragma unroll
            for (int nt = 0; nt < 2; nt++) {
                float bx = sb2n[8 * nt + 2 * tq], by = sb2n[8 * nt + 2 * tq + 1];
                float* cc = C4[nt];
                cc[0] = bx; cc[1] = by; cc[2] = bx; cc[3] = by;
                #pragma unroll
                for (int kt = 0; kt < 4; kt++) {
                    unsigned b0 = uw2n[(kt * 8 + tq) * 24 + 8 * nt + qid];
                    unsigned b1 = uw2n[(kt * 8 + tq + 4) * 24 + 8 * nt + qid];
                    mma16(cc, a4f[kt][0], a4f[kt][1], a4f[kt][2], a4f[kt][3], b0, b1);
                }
            }
            #pragma unroll
            for (int rr = 0; rr < 2; rr++) {
                int row = mt * 16 + rr * 8 + qid;
                bool rv = (wbase + row) < E;
                float s0 = C4[0][rr * 2 + 0], s1 = C4[0][rr * 2 + 1];
                float s2 = C4[1][rr * 2 + 0], s3 = C4[1][rr * 2 + 1];
                float p0 = __shfl_xor_sync(0xffffffffu, s0, 1);
                float p1 = __shfl_xor_sync(0xffffffffu, s1, 1);
                float p2 = __shfl_xor_sync(0xffffffffu, s2, 1);
                float p3 = __shfl_xor_sync(0xffffffffu, s3, 1);
                bool odd = (tq & 1);
                float v0 = odd ? p2 : s0;
                float v1 = odd ? p3 : s1;
                float v2 = odd ? s2 : p0;
                float v3 = odd ? s3 : p1;
                if (tq == 3) v3 = rv ? 1.0f : 0.f;
                if (!rv) { v0 = 0.f; v1 = 0.f; v2 = 0.f; if (tq != 3) v3 = 0.f; }
                int off = odd ? (6 + 2 * tq) : (2 * tq);
                *reinterpret_cast<float4*>(msgw + row * 20 + off) = make_float4(v0, v1, v2, v3);
            }
        }
        __syncwarp();

        // ---- segmented reduction over sorted rows, then few atomics ----
        {
            int rprev = __shfl_up_sync(0xffffffffu, r, 1);
            bool head = (lane == 0) || (r != rprev);
            unsigned hmask = __ballot_sync(0xffffffffu, head);
            int nseg = __popc(hmask);
            const float4* m4 = reinterpret_cast<const float4*>(msgw);
            int g = lane >> 3, sub = lane & 7, c4 = sub & 3;
            for (int s = 0; s < nseg; s += 4) {
                int sid = s + g;
                bool act = (sid < nseg);
                int start = act ? (int)__fns(hmask, 0, sid + 1) : 0;
                int end   = act ? ((sid + 1 < nseg) ? (int)__fns(hmask, 0, sid + 2) : 32) : 0;
                int rnode = __shfl_sync(0xffffffffu, r, act ? start : 0);
                float4 acc = make_float4(0.f, 0.f, 0.f, 0.f);
                for (int row = start + (sub >> 2); row < end; row += 2) {
                    float4 v = m4[row * 5 + c4];
                    acc.x += v.x; acc.y += v.y; acc.z += v.z; acc.w += v.w;
                }
                acc.x += __shfl_xor_sync(0xffffffffu, acc.x, 4);
                acc.y += __shfl_xor_sync(0xffffffffu, acc.y, 4);
                acc.z += __shfl_xor_sync(0xffffffffu, acc.z, 4);
                acc.w += __shfl_xor_sync(0xffffffffu, acc.w, 4);
                if (act && sub < 4)
                    red_add_v4(g_x2sum + (size_t)rnode * 16 + 4 * c4, acc.x, acc.y, acc.z, acc.w);
            }
        }
        __syncwarp();
    }
}

// ---------- fused: segmented node-mean + graph-mean + global MLP + fc1 ----
__global__ __launch_bounds__(256)
void graph_kernel(const float* __restrict__ u,
                  const float* __restrict__ gw1, const float* __restrict__ gb1,
                  const float* __restrict__ gw2, const float* __restrict__ gb2,
                  const float* __restrict__ f1w, const float* __restrict__ f1b,
                  int G)
{
    __shared__ float swg1[16 * 50];
    __shared__ float sbg1[50];
    __shared__ float swg2[50 * 15];
    __shared__ float sbg2[15];
    __shared__ float swf1[15 * 10];
    __shared__ float sbf1[10];
    __shared__ float sgin[8][16];
    __shared__ float sh[8][52];
    __shared__ float su[8][16];

    int tid = threadIdx.x;
    for (int i = tid; i < 800; i += 256) swg1[i] = gw1[i];
    for (int i = tid; i < 50;  i += 256) sbg1[i] = gb1[i];
    for (int i = tid; i < 750; i += 256) swg2[i] = gw2[i];
    for (int i = tid; i < 15;  i += 256) sbg2[i] = gb2[i];
    for (int i = tid; i < 150; i += 256) swf1[i] = f1w[i];
    for (int i = tid; i < 10;  i += 256) sbf1[i] = f1b[i];
    __syncthreads();

    int w = tid >> 5, lane = tid & 31;
    int gi = blockIdx.x * 8 + w;
    if (gi >= G) return;

    int lo = g_gstart[gi], hi = g_gstart[gi + 1];

    float acc[15];
    #pragma unroll
    for (int j = 0; j < 15; j++) acc[j] = 0.f;
    for (int n = lo + lane; n < hi; n += 32) {
        const float4* rp = reinterpret_cast<const float4*>(g_x2sum + (size_t)n * 16);
        float4 a = rp[0], b = rp[1], c = rp[2], d = rp[3];
        float inv = 1.f / fmaxf(d.w, 1.f);
        acc[0]  += a.x * inv; acc[1]  += a.y * inv; acc[2]  += a.z * inv; acc[3]  += a.w * inv;
        acc[4]  += b.x * inv; acc[5]  += b.y * inv; acc[6]  += b.z * inv; acc[7]  += b.w * inv;
        acc[8]  += c.x * inv; acc[9]  += c.y * inv; acc[10] += c.z * inv; acc[11] += c.w * inv;
        acc[12] += d.x * inv; acc[13] += d.y * inv; acc[14] += d.z * inv;
    }
    #pragma unroll
    for (int off = 16; off > 0; off >>= 1) {
        #pragma unroll
        for (int j = 0; j < 15; j++)
            acc[j] += __shfl_down_sync(0xffffffffu, acc[j], off);
    }
    if (lane == 0) {
        float invn = 1.f / fmaxf((float)(hi - lo), 1.f);
        sgin[w][0] = u[gi];
        #pragma unroll
        for (int j = 0; j < 15; j++) sgin[w][1 + j] = acc[j] * invn;
    }
    __syncwarp();

    float gin[16];
    #pragma unroll
    for (int k = 0; k < 16; k++) gin[k] = sgin[w][k];

    {
        int j = lane;
        float a0 = sbg1[j], a1 = 0.f;
        #pragma unroll
        for (int k = 0; k < 16; k += 2) {
            a0 += gin[k]     * swg1[k * 50 + j];
            a1 += gin[k + 1] * swg1[(k + 1) * 50 + j];
        }
        sh[w][j] = fmaxf(a0 + a1, 0.f);
        if (lane < 18) {
            int j2 = lane + 32;
            float b0 = sbg1[j2], b1 = 0.f;
            #pragma unroll
            for (int k = 0; k < 16; k += 2) {
                b0 += gin[k]     * swg1[k * 50 + j2];
                b1 += gin[k + 1] * swg1[(k + 1) * 50 + j2];
            }
            sh[w][j2] = fmaxf(b0 + b1, 0.f);
        }
    }
    __syncwarp();
    if (lane < D3) {
        float a0 = sbg2[lane], a1 = 0.f;
        #pragma unroll
        for (int k = 0; k < 50; k += 2) {
            a0 += sh[w][k]     * swg2[k * D3 + lane];
            a1 += sh[w][k + 1] * swg2[(k + 1) * D3 + lane];
        }
        su[w][lane] = a0 + a1;
    }
    __syncwarp();
    if (lane < D5) {
        float a = sbf1[lane];
        #pragma unroll
        for (int k = 0; k < D3; k++) a += su[w][k] * swf1[k * D5 + lane];
        g_z[gi * D5 + lane] = a;
        atomicAdd(&g_zstat[lane], a);
        atomicAdd(&g_zstat[D5 + lane], a * a);
    }
}

// -------------------- BN + ReLU + fc2 + log_softmax --------------------
__global__ void head_kernel(const float* __restrict__ bn_g, const float* __restrict__ bn_b,
                            const float* __restrict__ f2w, const float* __restrict__ f2b,
                            float* __restrict__ out, int G)
{
    int gi = blockIdx.x * blockDim.x + threadIdx.x;
    if (gi >= G) return;
    float invG = 1.f / (float)G;
    float zr[D5];
    #pragma unroll
    for (int j = 0; j < D5; j++) {
        float mean = g_zstat[j] * invG;
        float var  = g_zstat[D5 + j] * invG - mean * mean;
        float zn = (g_z[gi * D5 + j] - mean) * rsqrtf(var + EPS) * bn_g[j] + bn_b[j];
        zr[j] = fmaxf(zn, 0.f);
    }
    float lg[NC];
    float mx = -1e30f;
    #pragma unroll
    for (int j = 0; j < NC; j++) {
        float a = f2b[j];
        #pragma unroll
        for (int k = 0; k < D5; k++) a += zr[k] * f2w[k * NC + j];
        lg[j] = a;
        mx = fmaxf(mx, a);
    }
    float se = 0.f;
    #pragma unroll
    for (int j = 0; j < NC; j++) se += expf(lg[j] - mx);
    float lse = mx + logf(se);
    #pragma unroll
    for (int j = 0; j < NC; j++) out[gi * NC + j] = lg[j] - lse;
}

// -------------------- launch --------------------
extern "C" void kernel_launch(void* const* d_in, const int* in_sizes, int n_in,
                              void* d_out, int out_size)
{
    const float* x     = (const float*)d_in[0];
    const int*   ei    = (const int*)  d_in[1];
    const float* ea    = (const float*)d_in[2];
    const float* u     = (const float*)d_in[3];
    const int*   batch = (const int*)  d_in[4];
    const float* ew1 = (const float*)d_in[5];
    const float* eb1 = (const float*)d_in[6];
    const float* ew2 = (const float*)d_in[7];
    const float* eb2 = (const float*)d_in[8];
    const float* nw1 = (const float*)d_in[9];
    const float* nb1 = (const float*)d_in[10];
    const float* nw2 = (const float*)d_in[11];
    const float* nb2 = (const float*)d_in[12];
    const float* gw1 = (const float*)d_in[13];
    const float* gb1 = (const float*)d_in[14];
    const float* gw2 = (const float*)d_in[15];
    const float* gb2 = (const float*)d_in[16];
    const float* f1w = (const float*)d_in[17];
    const float* f1b = (const float*)d_in[18];
    const float* bn_g = (const float*)d_in[19];
    const float* bn_b = (const float*)d_in[20];
    const float* f2w = (const float*)d_in[21];
    const float* f2b = (const float*)d_in[22];
    float* out = (float*)d_out;

    int N = in_sizes[0] / 3;
    int E = in_sizes[1] / 2;
    int G = in_sizes[3];

    {
        int work = N * 4;
        int blocks = (work + 255) / 256;
        if (blocks > 2048) blocks = 2048;
        zero_kernel<<<blocks, 256>>>(x, batch, N, G);
    }
    {
        int blocks = (E + 255) / 256;
        if (blocks > 2048) blocks = 2048;
        hist_kernel<<<blocks, 256>>>(ei, E);
    }
    scan_kernel<<<1, 1024>>>(N);
    {
        int blocks = (E + 255) / 256;
        if (blocks > 2048) blocks = 2048;
        scatter_kernel<<<blocks, 256>>>(ei, ea, E);
    }
    {
        int ntiles = (E + 127) / 128;
        int blocks = 3 * 148;
        if (ntiles < blocks) blocks = ntiles;
        edge_mma_kernel<<<blocks, TPB>>>(ew1, eb1, ew2, eb2,
                                         nw1, nb1, nw2, nb2, E, ntiles);
    }
    graph_kernel<<<(G + 7) / 8, 256>>>(u, gw1, gb1, gw2, gb2, f1w, f1b, G);
    head_kernel<<<(G + 255) / 256, 256>>>(bn_g, bn_b, f2w, f2b, out, G);
}

// round 17
// speedup vs baseline: 2.4130x; 2.4130x over previous
#include <cuda_runtime.h>
#include <cuda_fp16.h>
#include <math.h>

#define MAXN 100000
#define MAXG 1000
#define H  50
#define D3 15
#define D5 10
#define NC 6
#define EPS 1e-5f
#define TPB 128

// -------- scratch (device globals) --------
__device__ unsigned g_x2sum[MAXN * 8];   // per-node: 16 fp16 (15 msg + count) as 8 f16x2 words
__device__ float g_z[MAXG * D5];
__device__ float g_zstat[2 * D5];
__device__ float g_x4[MAXN * 4];
__device__ int   g_gstart[MAXG + 1];

// -------- helpers --------
__device__ __forceinline__ unsigned packh2(float a, float b) {
    __half2 h = __floats2half2_rn(a, b);
    return *reinterpret_cast<unsigned*>(&h);
}
__device__ __forceinline__ unsigned packh2_relu(float a, float b) {
    return packh2(fmaxf(a, 0.f), fmaxf(b, 0.f));
}
__device__ __forceinline__ void mma16(float c[4], unsigned a0, unsigned a1, unsigned a2, unsigned a3,
                                      unsigned b0, unsigned b1) {
    asm volatile("mma.sync.aligned.m16n8k16.row.col.f32.f16.f16.f32 "
        "{%0,%1,%2,%3}, {%4,%5,%6,%7}, {%8,%9}, {%0,%1,%2,%3};"
        : "+f"(c[0]), "+f"(c[1]), "+f"(c[2]), "+f"(c[3])
        : "r"(a0), "r"(a1), "r"(a2), "r"(a3), "r"(b0), "r"(b1));
}
__device__ __forceinline__ void red_h2v2(unsigned* p, unsigned w0, unsigned w1) {
    asm volatile("red.global.add.noftz.v2.f16x2 [%0], {%1,%2};"
                 :: "l"(p), "r"(w0), "r"(w1) : "memory");
}

// -------------------- zero scratch + pad x + graph boundaries ------------
__global__ void zero_kernel(const float* __restrict__ x, const int* __restrict__ batch,
                            int N, int G) {
    int i = blockIdx.x * blockDim.x + threadIdx.x;
    int stride = gridDim.x * blockDim.x;
    uint4 z4 = make_uint4(0u, 0u, 0u, 0u);
    uint4* x2v = reinterpret_cast<uint4*>(g_x2sum);
    int n8 = N * 2;
    for (int k = i; k < n8; k += stride) x2v[k] = z4;
    for (int k = i; k < N; k += stride) {
        float4 v;
        v.x = x[3 * k]; v.y = x[3 * k + 1]; v.z = x[3 * k + 2]; v.w = 0.f;
        *reinterpret_cast<float4*>(g_x4 + 4 * (size_t)k) = v;
    }
    for (int k = i; k < N; k += stride) {
        int b = batch[k];
        int bn = (k + 1 < N) ? batch[k + 1] : G;
        if (k == 0)
            for (int g = 0; g <= b; g++) g_gstart[g] = 0;
        for (int g = b + 1; g <= bn; g++) g_gstart[g] = k + 1;
    }
    if (i < 2 * D5) g_zstat[i] = 0.f;
}

// -------------------- edge pipeline: fp16 m16n8k16, register-chained ------
__global__ __launch_bounds__(TPB, 3)
void edge_mma_kernel(const int* __restrict__ ei,
                     const float* __restrict__ ea,
                     const float* __restrict__ ew1, const float* __restrict__ eb1,
                     const float* __restrict__ ew2, const float* __restrict__ eb2,
                     const float* __restrict__ nw1, const float* __restrict__ nb1,
                     const float* __restrict__ nw2, const float* __restrict__ nb2,
                     int E, int ntiles)
{
    __shared__ unsigned uw1e[8 * 56];
    __shared__ unsigned uw2e[32 * 24];
    __shared__ unsigned uw1n[16 * 56];
    __shared__ unsigned uw2n[32 * 24];
    __shared__ float sb1e[56], sb2e[16], sb1n[56], sb2n[16];
    __shared__ unsigned ustg[4 * 32 * 12];

    int tid = threadIdx.x;

    for (int i = tid; i < 8 * 56; i += TPB) {
        int kp = i / 56, n = i % 56;
        int k0 = 2 * kp, k1 = 2 * kp + 1;
        float w0 = (k0 < 9 && n < 50) ? ew1[k0 * 50 + n] : 0.f;
        float w1 = (k1 < 9 && n < 50) ? ew1[k1 * 50 + n] : 0.f;
        uw1e[i] = packh2(w0, w1);
    }
    for (int i = tid; i < 32 * 24; i += TPB) {
        int kp = i / 24, n = i % 24;
        int k0 = 2 * kp, k1 = k0 + 1;
        float w0 = (k0 < 50 && n < 15) ? ew2[k0 * 15 + n] : 0.f;
        float w1 = (k1 < 50 && n < 15) ? ew2[k1 * 15 + n] : 0.f;
        uw2e[i] = packh2(w0, w1);
    }
    for (int i = tid; i < 16 * 56; i += TPB) {
        int kp = i / 56, n = i % 56;
        float w[2];
        #pragma unroll
        for (int h = 0; h < 2; h++) {
            int k = 2 * kp + h;
            int src = (k < 15) ? (3 + k) : ((k >= 16 && k < 19) ? (k - 16) : -1);
            w[h] = (src >= 0 && n < 50) ? nw1[src * 50 + n] : 0.f;
        }
        uw1n[i] = packh2(w[0], w[1]);
    }
    for (int i = tid; i < 32 * 24; i += TPB) {
        int kp = i / 24, n = i % 24;
        int k0 = 2 * kp, k1 = k0 + 1;
        float w0 = (k0 < 50 && n < 15) ? nw2[k0 * 15 + n] : 0.f;
        float w1 = (k1 < 50 && n < 15) ? nw2[k1 * 15 + n] : 0.f;
        uw2n[i] = packh2(w0, w1);
    }
    for (int i = tid; i < 56; i += TPB) sb1e[i] = (i < 50) ? eb1[i] : 0.f;
    for (int i = tid; i < 16; i += TPB) sb2e[i] = (i < 15) ? eb2[i] : 0.f;
    for (int i = tid; i < 56; i += TPB) sb1n[i] = (i < 50) ? nb1[i] : 0.f;
    for (int i = tid; i < 16; i += TPB) sb2n[i] = (i < 15) ? nb2[i] : 0.f;
    __syncthreads();

    int wid = tid >> 5, lane = tid & 31;
    int qid = lane >> 2, tq = lane & 3;
    unsigned* stg = ustg + wid * 384;

    stg[lane * 12 + 5] = 0u; stg[lane * 12 + 6] = 0u; stg[lane * 12 + 7] = 0u;
    __syncwarp();

    for (int t = blockIdx.x; t < ntiles; t += gridDim.x) {
        int wbase = t * 128 + wid * 32;
        int e = wbase + lane;
        int el = (e < E) ? e : (E - 1);
        int r = ei[el];
        int c = ei[E + el];
        float4 xr = *reinterpret_cast<const float4*>(g_x4 + 4 * (size_t)r);
        float4 xc4 = *reinterpret_cast<const float4*>(g_x4 + 4 * (size_t)c);
        float xc0 = xc4.x, xc1 = xc4.y, xc2 = xc4.z;
        float ea0 = ea[3 * el], ea1 = ea[3 * el + 1], ea2 = ea[3 * el + 2];

        {
            unsigned* sp = stg + lane * 12;
            sp[0] = packh2(xr.x, xr.y);
            sp[1] = packh2(xr.z, xc0);
            sp[2] = packh2(xc1, xc2);
            sp[3] = packh2(ea0, ea1);
            sp[4] = packh2(ea2, 0.f);
        }
        __syncwarp();

        // ---- L1 ----
        unsigned a2f[2][4][4];
        #pragma unroll
        for (int mt = 0; mt < 2; mt++) {
            unsigned a0 = stg[(16 * mt + qid) * 12 + tq];
            unsigned a1 = stg[(16 * mt + 8 + qid) * 12 + tq];
            unsigned a2 = stg[(16 * mt + qid) * 12 + tq + 4];
            unsigned a3 = stg[(16 * mt + 8 + qid) * 12 + tq + 4];
            float C1[7][4];
            #pragma unroll
            for (int nt = 0; nt < 7; nt++) {
                float bx = sb1e[8 * nt + 2 * tq], by = sb1e[8 * nt + 2 * tq + 1];
                C1[nt][0] = bx; C1[nt][1] = by; C1[nt][2] = bx; C1[nt][3] = by;
                unsigned b0 = uw1e[tq * 56 + 8 * nt + qid];
                unsigned b1 = uw1e[(tq + 4) * 56 + 8 * nt + qid];
                mma16(C1[nt], a0, a1, a2, a3, b0, b1);
            }
            #pragma unroll
            for (int kt = 0; kt < 4; kt++) {
                a2f[mt][kt][0] = packh2_relu(C1[2 * kt][0], C1[2 * kt][1]);
                a2f[mt][kt][1] = packh2_relu(C1[2 * kt][2], C1[2 * kt][3]);
                if (kt < 3) {
                    a2f[mt][kt][2] = packh2_relu(C1[2 * kt + 1][0], C1[2 * kt + 1][1]);
                    a2f[mt][kt][3] = packh2_relu(C1[2 * kt + 1][2], C1[2 * kt + 1][3]);
                } else {
                    a2f[mt][kt][2] = 0u; a2f[mt][kt][3] = 0u;
                }
            }
        }
        __syncwarp();

        // ---- L2 ----
        float C2[2][2][4];
        #pragma unroll
        for (int mt = 0; mt < 2; mt++)
            #pragma unroll
            for (int nt = 0; nt < 2; nt++) {
                float bx = sb2e[8 * nt + 2 * tq], by = sb2e[8 * nt + 2 * tq + 1];
                float* cc = C2[mt][nt];
                cc[0] = bx; cc[1] = by; cc[2] = bx; cc[3] = by;
                #pragma unroll
                for (int kt = 0; kt < 4; kt++) {
                    unsigned b0 = uw2e[(kt * 8 + tq) * 24 + 8 * nt + qid];
                    unsigned b1 = uw2e[(kt * 8 + tq + 4) * 24 + 8 * nt + qid];
                    mma16(cc, a2f[mt][kt][0], a2f[mt][kt][1], a2f[mt][kt][2], a2f[mt][kt][3], b0, b1);
                }
            }

        // ---- L3 A frags ----
        unsigned a3f[2][2][4];
        #pragma unroll
        for (int mt = 0; mt < 2; mt++) {
            a3f[mt][0][0] = packh2(C2[mt][0][0], C2[mt][0][1]);
            a3f[mt][0][1] = packh2(C2[mt][0][2], C2[mt][0][3]);
            a3f[mt][0][2] = packh2(C2[mt][1][0], C2[mt][1][1]);
            a3f[mt][0][3] = packh2(C2[mt][1][2], C2[mt][1][3]);
            int row0 = 16 * mt + qid, row1 = row0 + 8;
            float p0 = __shfl_sync(0xffffffffu, xc0, row0);
            float p1 = __shfl_sync(0xffffffffu, xc1, row0);
            float p2 = __shfl_sync(0xffffffffu, xc2, row0);
            float q0 = __shfl_sync(0xffffffffu, xc0, row1);
            float q1 = __shfl_sync(0xffffffffu, xc1, row1);
            float q2 = __shfl_sync(0xffffffffu, xc2, row1);
            unsigned a0 = (tq == 0) ? packh2(p0, p1) : ((tq == 1) ? packh2(p2, 0.f) : 0u);
            unsigned a1 = (tq == 0) ? packh2(q0, q1) : ((tq == 1) ? packh2(q2, 0.f) : 0u);
            a3f[mt][1][0] = a0; a3f[mt][1][1] = a1;
            a3f[mt][1][2] = 0u; a3f[mt][1][3] = 0u;
        }

        // ---- L3 + L4 + f16x2 scatter ----
        #pragma unroll
        for (int mt = 0; mt < 2; mt++) {
            float C3[7][4];
            #pragma unroll
            for (int nt = 0; nt < 7; nt++) {
                float bx = sb1n[8 * nt + 2 * tq], by = sb1n[8 * nt + 2 * tq + 1];
                C3[nt][0] = bx; C3[nt][1] = by; C3[nt][2] = bx; C3[nt][3] = by;
                #pragma unroll
                for (int kt = 0; kt < 2; kt++) {
                    unsigned b0 = uw1n[(kt * 8 + tq) * 56 + 8 * nt + qid];
                    unsigned b1 = uw1n[(kt * 8 + tq + 4) * 56 + 8 * nt + qid];
                    mma16(C3[nt], a3f[mt][kt][0], a3f[mt][kt][1], a3f[mt][kt][2], a3f[mt][kt][3], b0, b1);
                }
            }
            unsigned a4f[4][4];
            #pragma unroll
            for (int kt = 0; kt < 4; kt++) {
                a4f[kt][0] = packh2_relu(C3[2 * kt][0], C3[2 * kt][1]);
                a4f[kt][1] = packh2_relu(C3[2 * kt][2], C3[2 * kt][3]);
                if (kt < 3) {
                    a4f[kt][2] = packh2_relu(C3[2 * kt + 1][0], C3[2 * kt + 1][1]);
                    a4f[kt][3] = packh2_relu(C3[2 * kt + 1][2], C3[2 * kt + 1][3]);
                } else {
                    a4f[kt][2] = 0u; a4f[kt][3] = 0u;
                }
            }
            float C4[2][4];
            #pragma unroll
            for (int nt = 0; nt < 2; nt++) {
                float bx = sb2n[8 * nt + 2 * tq], by = sb2n[8 * nt + 2 * tq + 1];
                float* cc = C4[nt];
                cc[0] = bx; cc[1] = by; cc[2] = bx; cc[3] = by;
                #pragma unroll
                for (int kt = 0; kt < 4; kt++) {
                    unsigned b0 = uw2n[(kt * 8 + tq) * 24 + 8 * nt + qid];
                    unsigned b1 = uw2n[(kt * 8 + tq + 4) * 24 + 8 * nt + qid];
                    mma16(cc, a4f[kt][0], a4f[kt][1], a4f[kt][2], a4f[kt][3], b0, b1);
                }
            }
            // butterfly-pack 4 consecutive cols per lane, one red.v2.f16x2 (8 halves/edge total words)
            #pragma unroll
            for (int rr = 0; rr < 2; rr++) {
                int row = mt * 16 + rr * 8 + qid;
                int rnode = __shfl_sync(0xffffffffu, r, row);
                float s0 = C4[0][rr * 2 + 0], s1 = C4[0][rr * 2 + 1];
                float s2 = C4[1][rr * 2 + 0], s3 = C4[1][rr * 2 + 1];
                float p0 = __shfl_xor_sync(0xffffffffu, s0, 1);
                float p1 = __shfl_xor_sync(0xffffffffu, s1, 1);
                float p2 = __shfl_xor_sync(0xffffffffu, s2, 1);
                float p3 = __shfl_xor_sync(0xffffffffu, s3, 1);
                bool odd = (tq & 1);
                float v0 = odd ? p2 : s0;
                float v1 = odd ? p3 : s1;
                float v2 = odd ? s2 : p0;
                float v3 = odd ? s3 : p1;
                if (tq == 3) v3 = 1.0f;              // count at col 15
                if (wbase + row < E) {
                    int woff = (odd ? (6 + 2 * tq) : (2 * tq)) >> 1;  // f16x2 word offset
                    red_h2v2(g_x2sum + (size_t)rnode * 8 + woff,
                             packh2(v0, v1), packh2(v2, v3));
                }
            }
        }
    }
}

// ---------- fused: segmented node-mean + graph-mean + global MLP + fc1 ----
__global__ __launch_bounds__(256)
void graph_kernel(const float* __restrict__ u,
                  const float* __restrict__ gw1, const float* __restrict__ gb1,
                  const float* __restrict__ gw2, const float* __restrict__ gb2,
                  const float* __restrict__ f1w, const float* __restrict__ f1b,
                  int G)
{
    __shared__ float swg1[16 * 50];
    __shared__ float sbg1[50];
    __shared__ float swg2[50 * 15];
    __shared__ float sbg2[15];
    __shared__ float swf1[15 * 10];
    __shared__ float sbf1[10];
    __shared__ float sgin[8][16];
    __shared__ float sh[8][52];
    __shared__ float su[8][16];

    int tid = threadIdx.x;
    for (int i = tid; i < 800; i += 256) swg1[i] = gw1[i];
    for (int i = tid; i < 50;  i += 256) sbg1[i] = gb1[i];
    for (int i = tid; i < 750; i += 256) swg2[i] = gw2[i];
    for (int i = tid; i < 15;  i += 256) sbg2[i] = gb2[i];
    for (int i = tid; i < 150; i += 256) swf1[i] = f1w[i];
    for (int i = tid; i < 10;  i += 256) sbf1[i] = f1b[i];
    __syncthreads();

    int w = tid >> 5, lane = tid & 31;
    int gi = blockIdx.x * 8 + w;
    if (gi >= G) return;

    int lo = g_gstart[gi], hi = g_gstart[gi + 1];

    float acc[15];
    #pragma unroll
    for (int j = 0; j < 15; j++) acc[j] = 0.f;
    for (int n = lo + lane; n < hi; n += 32) {
        const uint4* rp = reinterpret_cast<const uint4*>(g_x2sum + (size_t)n * 8);
        uint4 a = rp[0], b = rp[1];
        float2 f0 = __half22float2(*reinterpret_cast<__half2*>(&a.x));
        float2 f1 = __half22float2(*reinterpret_cast<__half2*>(&a.y));
        float2 f2 = __half22float2(*reinterpret_cast<__half2*>(&a.z));
        float2 f3 = __half22float2(*reinterpret_cast<__half2*>(&a.w));
        float2 f4 = __half22float2(*reinterpret_cast<__half2*>(&b.x));
        float2 f5 = __half22float2(*reinterpret_cast<__half2*>(&b.y));
        float2 f6 = __half22float2(*reinterpret_cast<__half2*>(&b.z));
        float2 f7 = __half22float2(*reinterpret_cast<__half2*>(&b.w));
        float inv = 1.f / fmaxf(f7.y, 1.f);
        acc[0]  += f0.x * inv; acc[1]  += f0.y * inv;
        acc[2]  += f1.x * inv; acc[3]  += f1.y * inv;
        acc[4]  += f2.x * inv; acc[5]  += f2.y * inv;
        acc[6]  += f3.x * inv; acc[7]  += f3.y * inv;
        acc[8]  += f4.x * inv; acc[9]  += f4.y * inv;
        acc[10] += f5.x * inv; acc[11] += f5.y * inv;
        acc[12] += f6.x * inv; acc[13] += f6.y * inv;
        acc[14] += f7.x * inv;
    }
    #pragma unroll
    for (int off = 16; off > 0; off >>= 1) {
        #pragma unroll
        for (int j = 0; j < 15; j++)
            acc[j] += __shfl_down_sync(0xffffffffu, acc[j], off);
    }
    if (lane == 0) {
        float invn = 1.f / fmaxf((float)(hi - lo), 1.f);
        sgin[w][0] = u[gi];
        #pragma unroll
        for (int j = 0; j < 15; j++) sgin[w][1 + j] = acc[j] * invn;
    }
    __syncwarp();

    float gin[16];
    #pragma unroll
    for (int k = 0; k < 16; k++) gin[k] = sgin[w][k];

    {
        int j = lane;
        float a0 = sbg1[j], a1 = 0.f;
        #pragma unroll
        for (int k = 0; k < 16; k += 2) {
            a0 += gin[k]     * swg1[k * 50 + j];
            a1 += gin[k + 1] * swg1[(k + 1) * 50 + j];
        }
        sh[w][j] = fmaxf(a0 + a1, 0.f);
        if (lane < 18) {
            int j2 = lane + 32;
            float b0 = sbg1[j2], b1 = 0.f;
            #pragma unroll
            for (int k = 0; k < 16; k += 2) {
                b0 += gin[k]     * swg1[k * 50 + j2];
                b1 += gin[k + 1] * swg1[(k + 1) * 50 + j2];
            }
            sh[w][j2] = fmaxf(b0 + b1, 0.f);
        }
    }
    __syncwarp();
    if (lane < D3) {
        float a0 = sbg2[lane], a1 = 0.f;
        #pragma unroll
        for (int k = 0; k < 50; k += 2) {
            a0 += sh[w][k]     * swg2[k * D3 + lane];
            a1 += sh[w][k + 1] * swg2[(k + 1) * D3 + lane];
        }
        su[w][lane] = a0 + a1;
    }
    __syncwarp();
    if (lane < D5) {
        float a = sbf1[lane];
        #pragma unroll
        for (int k = 0; k < D3; k++) a += su[w][k] * swf1[k * D5 + lane];
        g_z[gi * D5 + lane] = a;
        atomicAdd(&g_zstat[lane], a);
        atomicAdd(&g_zstat[D5 + lane], a * a);
    }
}

// -------------------- BN + ReLU + fc2 + log_softmax --------------------
__global__ void head_kernel(const float* __restrict__ bn_g, const float* __restrict__ bn_b,
                            const float* __restrict__ f2w, const float* __restrict__ f2b,
                            float* __restrict__ out, int G)
{
    int gi = blockIdx.x * blockDim.x + threadIdx.x;
    if (gi >= G) return;
    float invG = 1.f / (float)G;
    float zr[D5];
    #pragma unroll
    for (int j = 0; j < D5; j++) {
        float mean = g_zstat[j] * invG;
        float var  = g_zstat[D5 + j] * invG - mean * mean;
        float zn = (g_z[gi * D5 + j] - mean) * rsqrtf(var + EPS) * bn_g[j] + bn_b[j];
        zr[j] = fmaxf(zn, 0.f);
    }
    float lg[NC];
    float mx = -1e30f;
    #pragma unroll
    for (int j = 0; j < NC; j++) {
        float a = f2b[j];
        #pragma unroll
        for (int k = 0; k < D5; k++) a += zr[k] * f2w[k * NC + j];
        lg[j] = a;
        mx = fmaxf(mx, a);
    }
    float se = 0.f;
    #pragma unroll
    for (int j = 0; j < NC; j++) se += expf(lg[j] - mx);
    float lse = mx + logf(se);
    #pragma unroll
    for (int j = 0; j < NC; j++) out[gi * NC + j] = lg[j] - lse;
}

// -------------------- launch --------------------
extern "C" void kernel_launch(void* const* d_in, const int* in_sizes, int n_in,
                              void* d_out, int out_size)
{
    const float* x     = (const float*)d_in[0];
    const int*   ei    = (const int*)  d_in[1];
    const float* ea    = (const float*)d_in[2];
    const float* u     = (const float*)d_in[3];
    const int*   batch = (const int*)  d_in[4];
    const float* ew1 = (const float*)d_in[5];
    const float* eb1 = (const float*)d_in[6];
    const float* ew2 = (const float*)d_in[7];
    const float* eb2 = (const float*)d_in[8];
    const float* nw1 = (const float*)d_in[9];
    const float* nb1 = (const float*)d_in[10];
    const float* nw2 = (const float*)d_in[11];
    const float* nb2 = (const float*)d_in[12];
    const float* gw1 = (const float*)d_in[13];
    const float* gb1 = (const float*)d_in[14];
    const float* gw2 = (const float*)d_in[15];
    const float* gb2 = (const float*)d_in[16];
    const float* f1w = (const float*)d_in[17];
    const float* f1b = (const float*)d_in[18];
    const float* bn_g = (const float*)d_in[19];
    const float* bn_b = (const float*)d_in[20];
    const float* f2w = (const float*)d_in[21];
    const float* f2b = (const float*)d_in[22];
    float* out = (float*)d_out;

    int N = in_sizes[0] / 3;
    int E = in_sizes[1] / 2;
    int G = in_sizes[3];

    {
        int work = N * 2;
        int blocks = (work + 255) / 256;
        if (blocks > 2048) blocks = 2048;
        zero_kernel<<<blocks, 256>>>(x, batch, N, G);
    }
    {
        int ntiles = (E + 127) / 128;
        int blocks = 3 * 148;
        if (ntiles < blocks) blocks = ntiles;
        edge_mma_kernel<<<blocks, TPB>>>(ei, ea, ew1, eb1, ew2, eb2,
                                         nw1, nb1, nw2, nb2, E, ntiles);
    }
    graph_kernel<<<(G + 7) / 8, 256>>>(u, gw1, gb1, gw2, gb2, f1w, f1b, G);
    head_kernel<<<(G + 255) / 256, 256>>>(bn_g, bn_b, f2w, f2b, out, G);
}